// round 1
// baseline (speedup 1.0000x reference)
#include <cuda_runtime.h>
#include <stdint.h>

// Problem constants
#define TOT_E      10       // 8 regular + 2 spike experts
#define SPIKE_E0   8
#define DIN        512
#define DHID       1024
#define DOUT       256
#define BTOK       32768
#define TSPK       16
#define NPAIRS     (BTOK * 2)      // 65536 (token, expert) pairs, top-k=2
#define MAX_TILES  522             // sum ceil(n_e/128) <= 65536/128 + 10
#define BM 128
#define BN 128
#define BK 32

// ----------------------------------------------------------------------------
// Device scratch (static globals — no runtime allocation allowed)
// ----------------------------------------------------------------------------
__device__ float g_h[(size_t)NPAIRS * DHID];    // 256 MB hidden activations
__device__ float g_z[(size_t)NPAIRS * DOUT];    // 64 MB expert outputs (weighted)
__device__ int   g_perm[NPAIRS];                // row -> token
__device__ float g_wgt[NPAIRS];                 // row -> combine weight
__device__ int   g_rowOf[NPAIRS];               // (token*2+k) -> row
__device__ int   g_topk_e[NPAIRS];
__device__ float g_topk_w[NPAIRS];
__device__ int   g_counts[TOT_E];
__device__ int   g_offsets[TOT_E + 1];
__device__ int   g_cursor[TOT_E];
__device__ int   g_tile_e[MAX_TILES];
__device__ int   g_tile_r0[MAX_TILES];
__device__ int   g_tile_r1[MAX_TILES];
__device__ int   g_num_tiles;

// ----------------------------------------------------------------------------
// Helpers
// ----------------------------------------------------------------------------
__device__ __forceinline__ uint32_t f2tf32(float f) {
    uint32_t r;
    asm("cvt.rna.tf32.f32 %0, %1;" : "=r"(r) : "f"(f));
    return r;
}

__device__ __forceinline__ void mma_tf32(float* c, const uint32_t* a, const uint32_t* b) {
    asm volatile(
        "mma.sync.aligned.m16n8k8.row.col.f32.tf32.tf32.f32 "
        "{%0,%1,%2,%3}, {%4,%5,%6,%7}, {%8,%9}, {%0,%1,%2,%3};"
        : "+f"(c[0]), "+f"(c[1]), "+f"(c[2]), "+f"(c[3])
        : "r"(a[0]), "r"(a[1]), "r"(a[2]), "r"(a[3]),
          "r"(b[0]), "r"(b[1]));
}

// ----------------------------------------------------------------------------
// 0. zero the histogram (graph replays reuse globals)
// ----------------------------------------------------------------------------
__global__ void zero_kernel() {
    if (threadIdx.x < TOT_E) g_counts[threadIdx.x] = 0;
}

// ----------------------------------------------------------------------------
// 1. Router: one warp per token
// ----------------------------------------------------------------------------
__global__ void router_kernel(const float* __restrict__ x,
                              const float* __restrict__ spike,
                              const float* __restrict__ Wr,
                              const float* __restrict__ br) {
    int warp = (blockIdx.x * blockDim.x + threadIdx.x) >> 5;
    int lane = threadIdx.x & 31;
    if (warp >= BTOK) return;
    const float* xr = x + (size_t)warp * DIN;

    float acc[TOT_E];
#pragma unroll
    for (int e = 0; e < TOT_E; e++) acc[e] = 0.f;

    for (int k = lane; k < DIN; k += 32) {
        float xv = xr[k];
        const float* wrow = Wr + k * TOT_E;
#pragma unroll
        for (int e = 0; e < TOT_E; e++) acc[e] += xv * wrow[e];
    }
#pragma unroll
    for (int e = 0; e < TOT_E; e++) {
#pragma unroll
        for (int off = 16; off; off >>= 1)
            acc[e] += __shfl_xor_sync(0xffffffffu, acc[e], off);
    }
    float sp = (lane < TSPK) ? spike[warp * TSPK + lane] : 0.f;
#pragma unroll
    for (int off = 16; off; off >>= 1)
        sp += __shfl_xor_sync(0xffffffffu, sp, off);

    if (lane == 0) {
        float avg = sp * (1.f / TSPK);
        float lg[TOT_E];
#pragma unroll
        for (int e = 0; e < TOT_E; e++)
            lg[e] = acc[e] + br[e] + (e >= SPIKE_E0 ? avg : 0.f);
        float m = lg[0];
#pragma unroll
        for (int e = 1; e < TOT_E; e++) m = fmaxf(m, lg[e]);
        float p[TOT_E];
        float Z = 0.f;
#pragma unroll
        for (int e = 0; e < TOT_E; e++) { p[e] = expf(lg[e] - m); Z += p[e]; }
        float invZ = 1.f / Z;
#pragma unroll
        for (int e = 0; e < TOT_E; e++) p[e] *= invZ;

        // top-2, jax tie-break (lowest index first) via strict >
        int e0 = 0;
#pragma unroll
        for (int e = 1; e < TOT_E; e++) if (p[e] > p[e0]) e0 = e;
        int e1 = (e0 == 0) ? 1 : 0;
#pragma unroll
        for (int e = 0; e < TOT_E; e++)
            if (e != e0 && p[e] > p[e1]) e1 = e;

        float s = p[e0] + p[e1] + 1e-9f;
        g_topk_e[2 * warp + 0] = e0;
        g_topk_e[2 * warp + 1] = e1;
        g_topk_w[2 * warp + 0] = p[e0] / s;
        g_topk_w[2 * warp + 1] = p[e1] / s;
        atomicAdd(&g_counts[e0], 1);
        atomicAdd(&g_counts[e1], 1);
    }
}

// ----------------------------------------------------------------------------
// 2. Prefix sums + tile table (single thread; tiny)
// ----------------------------------------------------------------------------
__global__ void offsets_kernel() {
    int off = 0;
    for (int e = 0; e < TOT_E; e++) {
        g_offsets[e] = off;
        g_cursor[e]  = off;
        off += g_counts[e];
    }
    g_offsets[TOT_E] = off;
    int nt = 0;
    for (int e = 0; e < TOT_E; e++) {
        int n  = g_counts[e];
        int r0 = g_offsets[e];
        for (int t = 0; t < n; t += BM) {
            g_tile_e[nt]  = e;
            g_tile_r0[nt] = r0 + t;
            int r1 = r0 + t + BM;
            int re = r0 + n;
            g_tile_r1[nt] = r1 < re ? r1 : re;
            nt++;
        }
    }
    g_num_tiles = nt;
}

// ----------------------------------------------------------------------------
// 3. Scatter pairs into expert-sorted rows
// ----------------------------------------------------------------------------
__global__ void scatter_kernel() {
    int i = blockIdx.x * blockDim.x + threadIdx.x;
    if (i >= NPAIRS) return;
    int e   = g_topk_e[i];
    int pos = atomicAdd(&g_cursor[e], 1);
    g_perm[pos]  = i >> 1;
    g_wgt[pos]   = g_topk_w[i];
    g_rowOf[i]   = pos;
}

// ----------------------------------------------------------------------------
// 4. Grouped GEMM: C[rows, N] = act(A[rows, K] @ W[e] + bias[e]) (* wgt)
//    TF32 mma.sync, BM=128 BN=128 BK=32, 8 warps (2x4), warp tile 64x32
// ----------------------------------------------------------------------------
template<int KDIM, int NDIM, bool GATHER, bool RELU, bool SCALE>
__global__ __launch_bounds__(256)
void gemm_kernel(const float* __restrict__ Asrc,
                 const float* __restrict__ W,
                 const float* __restrict__ bias) {
    int bt = blockIdx.x;
    if (bt >= g_num_tiles) return;
    int e  = g_tile_e[bt];
    int r0 = g_tile_r0[bt];
    int r1 = g_tile_r1[bt];
    int n0 = blockIdx.y * BN;

    const float* Aptr = GATHER ? Asrc : g_h;
    float*       Out  = RELU ? g_h : g_z;
    const float* Wexp = W + (size_t)e * KDIM * NDIM;
    const float* be   = bias + e * NDIM;

    __shared__ uint32_t As[BM][36];    // padded: conflict-free frag reads
    __shared__ uint32_t Bs[BK][132];

    int tid  = threadIdx.x;
    int lane = tid & 31;
    int wid  = tid >> 5;
    int gidl = lane >> 2;
    int tg   = lane & 3;
    int wm   = (wid >> 2) * 64;
    int wn   = (wid & 3) * 32;

    float acc[4][4][4];
#pragma unroll
    for (int a = 0; a < 4; a++)
#pragma unroll
        for (int b = 0; b < 4; b++)
#pragma unroll
            for (int c = 0; c < 4; c++) acc[a][b][c] = 0.f;

    int la_m = tid >> 3;          // 0..31
    int la_k = (tid & 7) * 4;     // 0..28
    int lb_k = tid >> 5;          // 0..7
    int lb_n = (tid & 31) * 4;    // 0..124

    for (int kt = 0; kt < KDIM; kt += BK) {
        // ---- stage A (gathered or direct), convert to tf32 ----
#pragma unroll
        for (int p = 0; p < 4; p++) {
            int m = la_m + p * 32;
            int r = r0 + m;
            float4 v = make_float4(0.f, 0.f, 0.f, 0.f);
            if (r < r1) {
                const float* ap;
                if (GATHER) ap = Aptr + (size_t)g_perm[r] * KDIM + kt + la_k;
                else        ap = Aptr + (size_t)r * KDIM + kt + la_k;
                v = *reinterpret_cast<const float4*>(ap);
            }
            uint4 t4;
            t4.x = f2tf32(v.x); t4.y = f2tf32(v.y);
            t4.z = f2tf32(v.z); t4.w = f2tf32(v.w);
            *reinterpret_cast<uint4*>(&As[m][la_k]) = t4;
        }
        // ---- stage B ----
#pragma unroll
        for (int p = 0; p < 4; p++) {
            int k = lb_k + p * 8;
            const float* bp = Wexp + (size_t)(kt + k) * NDIM + n0 + lb_n;
            float4 v = *reinterpret_cast<const float4*>(bp);
            uint4 t4;
            t4.x = f2tf32(v.x); t4.y = f2tf32(v.y);
            t4.z = f2tf32(v.z); t4.w = f2tf32(v.w);
            *reinterpret_cast<uint4*>(&Bs[k][lb_n]) = t4;
        }
        __syncthreads();

#pragma unroll
        for (int kk = 0; kk < BK; kk += 8) {
            uint32_t af[4][4], bf[4][2];
#pragma unroll
            for (int mi = 0; mi < 4; mi++) {
                int m = wm + mi * 16;
                af[mi][0] = As[m + gidl    ][kk + tg    ];
                af[mi][1] = As[m + gidl + 8][kk + tg    ];
                af[mi][2] = As[m + gidl    ][kk + tg + 4];
                af[mi][3] = As[m + gidl + 8][kk + tg + 4];
            }
#pragma unroll
            for (int ni = 0; ni < 4; ni++) {
                int n = wn + ni * 8;
                bf[ni][0] = Bs[kk + tg    ][n + gidl];
                bf[ni][1] = Bs[kk + tg + 4][n + gidl];
            }
#pragma unroll
            for (int mi = 0; mi < 4; mi++)
#pragma unroll
                for (int ni = 0; ni < 4; ni++)
                    mma_tf32(acc[mi][ni], af[mi], bf[ni]);
        }
        __syncthreads();
    }

    // ---- epilogue ----
#pragma unroll
    for (int mi = 0; mi < 4; mi++) {
#pragma unroll
        for (int ri = 0; ri < 2; ri++) {
            int r = r0 + wm + mi * 16 + gidl + ri * 8;
            if (r >= r1) continue;
            float sc = SCALE ? g_wgt[r] : 1.f;
            float* orow = Out + (size_t)r * NDIM;
#pragma unroll
            for (int ni = 0; ni < 4; ni++) {
                int c  = n0 + wn + ni * 8 + 2 * tg;
                float v0 = acc[mi][ni][ri * 2 + 0] + be[c];
                float v1 = acc[mi][ni][ri * 2 + 1] + be[c + 1];
                if (RELU) { v0 = fmaxf(v0, 0.f); v1 = fmaxf(v1, 0.f); }
                if (SCALE) { v0 *= sc; v1 *= sc; }
                orow[c]     = v0;
                orow[c + 1] = v1;
            }
        }
    }
}

// ----------------------------------------------------------------------------
// 5. Combine: out[t] = z[row(t,0)] + z[row(t,1)]  (weights already folded)
// ----------------------------------------------------------------------------
__global__ void combine_kernel(float* __restrict__ out) {
    int i = blockIdx.x * blockDim.x + threadIdx.x;
    if (i >= BTOK * DOUT) return;
    int t = i / DOUT;
    int c = i % DOUT;
    int ra = g_rowOf[2 * t + 0];
    int rb = g_rowOf[2 * t + 1];
    out[i] = g_z[(size_t)ra * DOUT + c] + g_z[(size_t)rb * DOUT + c];
}

// ----------------------------------------------------------------------------
// Launch
// ----------------------------------------------------------------------------
extern "C" void kernel_launch(void* const* d_in, const int* in_sizes, int n_in,
                              void* d_out, int out_size) {
    const float* x     = (const float*)d_in[0];
    const float* spike = (const float*)d_in[1];
    const float* Wr    = (const float*)d_in[2];
    const float* br    = (const float*)d_in[3];
    const float* W1    = (const float*)d_in[4];
    const float* b1    = (const float*)d_in[5];
    const float* W2    = (const float*)d_in[6];
    const float* b2    = (const float*)d_in[7];
    float* out = (float*)d_out;

    zero_kernel<<<1, 32>>>();
    router_kernel<<<BTOK / 8, 256>>>(x, spike, Wr, br);
    offsets_kernel<<<1, 1>>>();
    scatter_kernel<<<NPAIRS / 256, 256>>>();
    // GEMM1: h = relu(Xg @ W1[e] + b1[e]), N=1024 -> 8 N-tiles
    gemm_kernel<DIN, DHID, true, true, false>
        <<<dim3(MAX_TILES, DHID / BN), 256>>>(x, W1, b1);
    // GEMM2: z = (h @ W2[e] + b2[e]) * wgt, N=256 -> 2 N-tiles
    gemm_kernel<DHID, DOUT, false, false, true>
        <<<dim3(MAX_TILES, DOUT / BN), 256>>>(nullptr, W2, b2);
    combine_kernel<<<(BTOK * DOUT) / 256, 256>>>(out);
}